// round 14
// baseline (speedup 1.0000x reference)
#include <cuda_runtime.h>
#include <cuda_bf16.h>
#include <cstdint>

#define BB  2
#define SS  4096
#define CC  640
#define HH  10
#define DHH 64
#define BH  (BB*HH)
#define NHS4 (BB*SS*CC/4)
#define NW4  (CC*CC/4)
#define NOB  (BH*SS*DHH)

// ---------------- scratch (no allocations allowed) ----------------
__device__ __align__(16) __nv_bfloat16 hsb[BB*SS*CC];
__device__ __align__(16) __nv_bfloat16 wqb[CC*CC];      // Wq * qscale
__device__ __align__(16) __nv_bfloat16 wkb[CC*CC];
__device__ __align__(16) __nv_bfloat16 wvb[CC*CC];
__device__ __align__(16) __nv_bfloat16 wob[CC*CC];
__device__ __align__(16) __nv_bfloat16 g_qb[NOB];       // Q bf16 [bh][s][d] (prescaled)
__device__ __align__(16) __nv_bfloat16 g_kb[NOB];       // K bf16 [bh][s][d]
__device__ __align__(16) __nv_bfloat16 g_vt[NOB];       // V^T bf16 [bh][d][s]
__device__ __align__(16) __nv_bfloat16 g_ob[NOB];       // attn out bf16 [bh][s][d]
__device__ __align__(16) __nv_bfloat16 g_po[2][NOB];    // split-K partial O (bf16, unnorm)
__device__ __align__(16) float g_pl[2][BH*SS];          // split-K partial row sums

// ---------------- helpers ----------------
__device__ __forceinline__ uint32_t smem_u32(const void* p) {
    uint32_t a;
    asm("{ .reg .u64 t; cvta.to.shared.u64 t, %1; cvt.u32.u64 %0, t; }" : "=r"(a) : "l"(p));
    return a;
}
__device__ __forceinline__ uint32_t swz(uint32_t r, uint32_t cb) {
    return r * 128u + ((cb ^ (r & 7u)) << 4);
}
__device__ __forceinline__ uint32_t pkbf(float a, float b) {
    __nv_bfloat162 h = __float22bfloat162_rn(make_float2(a, b));
    return *(uint32_t*)&h;
}
__device__ __forceinline__ float ex2(float x) {
    float y;
    asm("ex2.approx.ftz.f32 %0, %1;" : "=f"(y) : "f"(x));
    return y;
}

#define LDSM4(R0, R1, R2, R3, A)                                                   \
    asm volatile("ldmatrix.sync.aligned.m8n8.x4.shared.b16 {%0,%1,%2,%3}, [%4];"   \
                 : "=r"(R0), "=r"(R1), "=r"(R2), "=r"(R3) : "r"(A))

#define MMA(C, A, B0, B1)                                                          \
    asm volatile("mma.sync.aligned.m16n8k16.row.col.f32.bf16.bf16.f32 "            \
                 "{%0,%1,%2,%3}, {%4,%5,%6,%7}, {%8,%9}, {%0,%1,%2,%3};"           \
                 : "+f"((C)[0]), "+f"((C)[1]), "+f"((C)[2]), "+f"((C)[3])          \
                 : "r"((A)[0]), "r"((A)[1]), "r"((A)[2]), "r"((A)[3]),             \
                   "r"(B0), "r"(B1))

#define CPA(D, S)  asm volatile("cp.async.cg.shared.global [%0], [%1], 16;" :: "r"(D), "l"(S))
#define CPC()      asm volatile("cp.async.commit_group;" ::: "memory")
#define CPW0()     asm volatile("cp.async.wait_group 0;" ::: "memory")
#define CPW1()     asm volatile("cp.async.wait_group 1;" ::: "memory")

// ---------------- fp32 -> bf16 convert (MLP=4) ----------------
#define CVT_TOT (NHS4 + 4 * NW4)
#define CVT_Q   (CVT_TOT / 4)
__global__ void __launch_bounds__(256) cvt_all(const float* __restrict__ hs,
                                               const float* __restrict__ Wq,
                                               const float* __restrict__ Wk,
                                               const float* __restrict__ Wv,
                                               const float* __restrict__ Wo,
                                               float qscale) {
    int i0 = blockIdx.x * 256 + threadIdx.x;
    if (i0 >= CVT_Q) return;
#pragma unroll
    for (int q = 0; q < 4; q++) {
        int i = i0 + q * CVT_Q;
        const float* src;
        __nv_bfloat16* dst;
        float sc = 1.f;
        int off;
        if (i < NHS4) {
            src = hs; dst = hsb; off = i;
        } else {
            int j = i - NHS4;
            int sel = j / NW4;
            off = j - sel * NW4;
            src = (sel == 0) ? Wq : (sel == 1) ? Wk : (sel == 2) ? Wv : Wo;
            dst = (sel == 0) ? wqb : (sel == 1) ? wkb : (sel == 2) ? wvb : wob;
            if (sel == 0) sc = qscale;
        }
        float4 v = ((const float4*)src)[off];
        uint2 u;
        u.x = pkbf(v.x * sc, v.y * sc);
        u.y = pkbf(v.z * sc, v.w * sc);
        ((uint2*)dst)[off] = u;
    }
}

// common fragment addressing
#define FRAG_SETUP()                                                               \
    const uint32_t ar  = (uint32_t)((wm >> 1) + ((lane & 15) >> 1));               \
    const uint32_t acb = (uint32_t)((lane & 1) * 4);                               \
    const uint32_t akc = (uint32_t)(lane >> 4);                                    \
    const uint32_t nlb = (uint32_t)(wn + (lane & 7) + ((lane >> 4) << 3));         \
    const uint32_t nr  = nlb >> 1;                                                 \
    const uint32_t ncb = ((nlb & 1) << 2) + ((lane >> 3) & 1)

// ============================================================================
// Fused QKV projection: grid (64, 10), 256 threads, 2 CTAs/SM.
// C tile 128m x 64n x 3 outputs. BK=32, 5 stages x (A 8K | Bq 4K | Bk 4K | Bv 4K)
// = 102400B dynamic smem. 2 chunks per barrier, wait->barrier->prefetch->consume.
// Per chunk: 4 A-LDSM + 12 B-LDSM + 48 MMA.
// ============================================================================
__global__ void __launch_bounds__(256, 2) projqkv_tc() {
    extern __shared__ __align__(128) char arena[];
    const uint32_t base = smem_u32(arena);

    const int tid = threadIdx.x, lane = tid & 31, w = tid >> 5;
    const int wm = (w >> 1) * 32, wn = (w & 1) * 32;
    const int h = blockIdx.y, m0 = blockIdx.x * 128;
    const int n0 = h * 64;

    const int arow = tid >> 1, apart = tid & 1;
    const uint32_t adst0 = swz(arow >> 1, (arow & 1) * 4 + apart * 2);
    const uint32_t adst1 = swz(arow >> 1, (arow & 1) * 4 + apart * 2 + 1);
    const int bn = tid >> 2, bkc = tid & 3;
    const uint32_t bdst = swz(bn >> 1, (bn & 1) * 4 + bkc);

#define QKV_PF(c, stg) do {                                                        \
        uint32_t so = base + (stg) * 20480;                                        \
        const __nv_bfloat16* as = hsb + (size_t)(m0 + arow) * CC + (c) * 32 + apart * 16; \
        CPA(so + adst0, as);                                                       \
        CPA(so + adst1, as + 8);                                                   \
        size_t boff = (size_t)(n0 + bn) * CC + (c) * 32 + bkc * 8;                 \
        CPA(so + 8192 + bdst, wqb + boff);                                         \
        CPA(so + 12288 + bdst, wkb + boff);                                        \
        CPA(so + 16384 + bdst, wvb + boff);                                        \
        CPC();                                                                     \
    } while (0)

#define QKV_CONSUME(STG) do {                                                      \
        uint32_t ab = base + (STG) * 20480;                                        \
        _Pragma("unroll")                                                          \
        for (int ks = 0; ks < 2; ks++) {                                           \
            uint32_t a0[4], a1[4];                                                 \
            LDSM4(a0[0], a0[1], a0[2], a0[3], ab + swz(ar,     acb + akc + ks*2)); \
            LDSM4(a1[0], a1[1], a1[2], a1[3], ab + swz(ar + 8, acb + akc + ks*2)); \
            _Pragma("unroll")                                                      \
            for (int jj = 0; jj < 2; jj++) {                                       \
                _Pragma("unroll")                                                  \
                for (int o = 0; o < 3; o++) {                                      \
                    uint32_t b0, b1, b2, b3;                                       \
                    LDSM4(b0, b1, b2, b3,                                          \
                          ab + 8192 + o * 4096 + swz(nr + jj * 8, ncb + ks * 2));  \
                    MMA(cc[o][0][jj * 2], a0, b0, b1);                             \
                    MMA(cc[o][0][jj * 2 + 1], a0, b2, b3);                         \
                    MMA(cc[o][1][jj * 2], a1, b0, b1);                             \
                    MMA(cc[o][1][jj * 2 + 1], a1, b2, b3);                         \
                }                                                                  \
            }                                                                      \
        }                                                                          \
    } while (0)

    FRAG_SETUP();

    float cc[3][2][4][4];
#pragma unroll
    for (int o = 0; o < 3; o++)
#pragma unroll
        for (int mi = 0; mi < 2; mi++)
#pragma unroll
            for (int nc = 0; nc < 4; nc++)
#pragma unroll
                for (int q = 0; q < 4; q++) cc[o][mi][nc][q] = 0.f;

    QKV_PF(0, 0);
    QKV_PF(1, 1);
    QKV_PF(2, 2);
    {
        int st0 = 0;
        for (int sc = 0; sc < 10; sc++) {
            if (sc < 9) CPW1(); else CPW0();
            __syncthreads();
            int pf0 = st0 + 3; if (pf0 >= 5) pf0 -= 5;
            int pf1 = st0 + 4; if (pf1 >= 5) pf1 -= 5;
            if (sc <= 8) QKV_PF(2 * sc + 3, pf0);
            if (sc <= 7) QKV_PF(2 * sc + 4, pf1);
            int st1 = st0 + 1; if (st1 >= 5) st1 -= 5;
            QKV_CONSUME(st0);
            QKV_CONSUME(st1);
            st0 += 2; if (st0 >= 5) st0 -= 5;
        }
    }

    const int g = lane >> 2, c2 = (lane & 3) * 2;
    const int b_ = m0 >> 12;
    const size_t rowbase = (size_t)(b_ * HH + h) * SS;

    // Q and K epilogues (bf16 row-major)
#pragma unroll
    for (int o = 0; o < 2; o++) {
        __nv_bfloat16* dst = (o == 0) ? g_qb : g_kb;
#pragma unroll
        for (int mi = 0; mi < 2; mi++) {
            int r_lo = m0 + wm + mi * 16 + g, r_hi = r_lo + 8;
            __nv_bfloat16* plo = dst + (rowbase + (r_lo & (SS - 1))) * DHH;
            __nv_bfloat16* phi = dst + (rowbase + (r_hi & (SS - 1))) * DHH;
#pragma unroll
            for (int nc = 0; nc < 4; nc++) {
                int d = wn + nc * 8 + c2;
                *(uint32_t*)(plo + d) = pkbf(cc[o][mi][nc][0], cc[o][mi][nc][1]);
                *(uint32_t*)(phi + d) = pkbf(cc[o][mi][nc][2], cc[o][mi][nc][3]);
            }
        }
    }

    // V epilogue: staged transpose (stt[d 64][m 128] pitch 136)
    __syncthreads();
    __nv_bfloat16* stt = (__nv_bfloat16*)arena;
#pragma unroll
    for (int mi = 0; mi < 2; mi++) {
        int ml = wm + mi * 16 + g, mh = ml + 8;
#pragma unroll
        for (int nc = 0; nc < 4; nc++) {
            int d = wn + nc * 8 + c2;
            stt[d * 136 + ml]       = __float2bfloat16(cc[2][mi][nc][0]);
            stt[(d + 1) * 136 + ml] = __float2bfloat16(cc[2][mi][nc][1]);
            stt[d * 136 + mh]       = __float2bfloat16(cc[2][mi][nc][2]);
            stt[(d + 1) * 136 + mh] = __float2bfloat16(cc[2][mi][nc][3]);
        }
    }
    __syncthreads();
    {
        const int row = tid >> 2, part = tid & 3;
        const int s_base = m0 & (SS - 1);
        __nv_bfloat16* dst = g_vt + ((size_t)(b_ * HH + h) * DHH + row) * SS + s_base + part * 32;
        const uint4* srcp = (const uint4*)(stt + row * 136 + part * 32);
#pragma unroll
        for (int i = 0; i < 4; i++)
            ((uint4*)dst)[i] = srcp[i];
    }
#undef QKV_PF
#undef QKV_CONSUME
}

// ---------------- flash attention: bf16, split-K, 3-stage ring --------------
// grid (32, 20, 2), 256 threads. 3 stages x 32768B = 98304B dynamic smem.
// Deferred softmax reduction: quad-shuffles once after the loop.
__global__ void __launch_bounds__(256, 2) attn_tc() {
    extern __shared__ __align__(128) char arena[];
    const uint32_t base = smem_u32(arena);

    const int tid = threadIdx.x, lane = tid & 31, w = tid >> 5;
    const int s0 = blockIdx.x * 128, bh = blockIdx.y, z = blockIdx.z;
    const int k_base = z * (SS / 2);
    const __nv_bfloat16* Qg = g_qb + (size_t)bh * SS * DHH;
    const __nv_bfloat16* Kg = g_kb + (size_t)bh * SS * DHH;
    const __nv_bfloat16* Vg = g_vt + (size_t)bh * DHH * SS;

    // stage Q bf16 tile [128][64] into stage-2 region (offset 65536)
    {
        int row = tid >> 1, half = tid & 1;
        const uint4* src = (const uint4*)(Qg + (size_t)(s0 + row) * DHH + half * 32);
#pragma unroll
        for (int i = 0; i < 4; i++)
            *(uint4*)(arena + 65536 + swz(row, half * 4 + i)) = src[i];
    }
    __syncthreads();

    uint32_t aq[4][4];
    {
        uint32_t r = w * 16 + (lane & 7) + (lane & 8);
#pragma unroll
        for (int ks = 0; ks < 4; ks++) {
            uint32_t cb = ks * 2 + (lane >> 4);
            LDSM4(aq[ks][0], aq[ks][1], aq[ks][2], aq[ks][3], base + 65536 + swz(r, cb));
        }
    }

    const int prow = tid >> 2, pcb = (tid & 3) * 2;
#define PFS(T, stg) do {                                                           \
        uint32_t so = base + (stg) * 32768;                                        \
        int j0 = k_base + (T) * 128;                                               \
        _Pragma("unroll") for (int sub = 0; sub < 2; sub++) {                      \
            uint32_t ko = so + sub * 16384, vo = ko + 8192;                        \
            const __nv_bfloat16* ks_ = Kg + (size_t)(j0 + sub * 64 + prow) * DHH;  \
            const __nv_bfloat16* vs_ = Vg + (size_t)prow * SS + j0 + sub * 64;     \
            _Pragma("unroll") for (int i = 0; i < 2; i++) {                        \
                CPA(ko + swz(prow, pcb + i), ks_ + (pcb + i) * 8);                 \
                CPA(vo + swz(prow, pcb + i), vs_ + (pcb + i) * 8);                 \
            }                                                                      \
        }                                                                          \
        CPC();                                                                     \
    } while (0)

    PFS(0, 0);
    PFS(1, 1);

    float co[8][4];
#pragma unroll
    for (int j = 0; j < 8; j++)
#pragma unroll
        for (int q = 0; q < 4; q++) co[j][q] = 0.f;
    float lacc_lo = 0.f, lacc_hi = 0.f;   // per-thread partial sums (reduced at end)

    const uint32_t brow = (lane & 7) + ((lane >> 4) << 3);
    const uint32_t bsel = (lane >> 3) & 1;

    int st = 0, pfst = 2;
    for (int T = 0; T < 16; T++) {
        if (T < 15) CPW1(); else CPW0();
        __syncthreads();
        if (T < 14) PFS(T + 2, pfst);
        const uint32_t stg = base + st * 32768;
        st = (st == 2) ? 0 : st + 1;
        pfst = (pfst == 2) ? 0 : pfst + 1;

#pragma unroll
        for (int sub = 0; sub < 2; sub++) {
            uint32_t kb = stg + sub * 16384, vb = kb + 8192;

            // S = Q K^T
            float cs[8][4];
#pragma unroll
            for (int j = 0; j < 8; j++)
#pragma unroll
                for (int q = 0; q < 4; q++) cs[j][q] = 0.f;
#pragma unroll
            for (int ks = 0; ks < 4; ks++) {
                uint32_t bc = ks * 2 + bsel;
#pragma unroll
                for (int j = 0; j < 8; j += 2) {
                    uint32_t b0, b1, b2, b3;
                    LDSM4(b0, b1, b2, b3, kb + swz(j * 8 + brow, bc));
                    MMA(cs[j], aq[ks], b0, b1);
                    MMA(cs[j + 1], aq[ks], b2, b3);
                }
            }

            // softmax: exp only; quad-reduction deferred to after the loop
            uint32_t pa[4][4];
#pragma unroll
            for (int j = 0; j < 8; j++) {
                float e0 = ex2(cs[j][0]), e1 = ex2(cs[j][1]);
                float e2 = ex2(cs[j][2]), e3 = ex2(cs[j][3]);
                lacc_lo += e0 + e1; lacc_hi += e2 + e3;
                pa[j >> 1][(j & 1) * 2 + 0] = pkbf(e0, e1);
                pa[j >> 1][(j & 1) * 2 + 1] = pkbf(e2, e3);
            }

            // O += P V
#pragma unroll
            for (int kc = 0; kc < 4; kc++) {
                uint32_t bc = kc * 2 + bsel;
#pragma unroll
                for (int j = 0; j < 8; j += 2) {
                    uint32_t b0, b1, b2, b3;
                    LDSM4(b0, b1, b2, b3, vb + swz(j * 8 + brow, bc));
                    MMA(co[j], pa[kc], b0, b1);
                    MMA(co[j + 1], pa[kc], b2, b3);
                }
            }
        }
    }
#undef PFS

    // final quad reduction (linear, safe to defer)
    lacc_lo += __shfl_xor_sync(0xffffffffu, lacc_lo, 1);
    lacc_lo += __shfl_xor_sync(0xffffffffu, lacc_lo, 2);
    lacc_hi += __shfl_xor_sync(0xffffffffu, lacc_hi, 1);
    lacc_hi += __shfl_xor_sync(0xffffffffu, lacc_hi, 2);

    // epilogue: store unnormalized bf16 partials + fp32 row sums
    const int g = lane >> 2, c2 = (lane & 3) * 2;
    const int r_lo = s0 + w * 16 + g, r_hi = r_lo + 8;
    __nv_bfloat16* plo = g_po[z] + ((size_t)bh * SS + r_lo) * DHH;
    __nv_bfloat16* phi = g_po[z] + ((size_t)bh * SS + r_hi) * DHH;
#pragma unroll
    for (int j = 0; j < 8; j++) {
        int col = j * 8 + c2;
        *(uint32_t*)(plo + col) = pkbf(co[j][0], co[j][1]);
        *(uint32_t*)(phi + col) = pkbf(co[j][2], co[j][3]);
    }
    g_pl[z][(size_t)bh * SS + r_lo] = lacc_lo;
    g_pl[z][(size_t)bh * SS + r_hi] = lacc_hi;
}

// ---------------- split-K combine: g_ob = bf16((po0+po1)/(l0+l1)) ----------
__global__ void __launch_bounds__(256) combine_k(int n8) {
    int i = blockIdx.x * 256 + threadIdx.x;
    if (i >= n8) return;
    int row = i >> 3;
    float l = g_pl[0][row] + g_pl[1][row];
    float inv = 1.f / l;
    uint4 a = ((const uint4*)g_po[0])[i];
    uint4 b = ((const uint4*)g_po[1])[i];
    uint4 o;
    const uint32_t* ap = &a.x;
    const uint32_t* bp = &b.x;
    uint32_t* op = &o.x;
#pragma unroll
    for (int q = 0; q < 4; q++) {
        float2 fa = __bfloat1622float2(*(const __nv_bfloat162*)&ap[q]);
        float2 fb = __bfloat1622float2(*(const __nv_bfloat162*)&bp[q]);
        op[q] = pkbf((fa.x + fb.x) * inv, (fa.y + fb.y) * inv);
    }
    ((uint4*)g_ob)[i] = o;
}

// ============================================================================
// GEMM v4 (unchanged): outproj. 128m x 64n, BK=32, 5 stages x 12288B.
// ============================================================================
#define V4_PF(ASRC, BSRC, stg) do {                                               \
        uint32_t ao = base + (stg) * 12288, bo = ao + 8192;                        \
        CPA(ao + adst0, (ASRC));                                                   \
        CPA(ao + adst1, (ASRC) + 8);                                               \
        CPA(bo + bdst, (BSRC));                                                    \
        CPC();                                                                     \
    } while (0)

#define V4_CONSUME(STG) do {                                                       \
        uint32_t ab = base + (STG) * 12288, bb = ab + 8192;                        \
        _Pragma("unroll")                                                          \
        for (int ks = 0; ks < 2; ks++) {                                           \
            uint32_t a0[4], a1[4];                                                 \
            LDSM4(a0[0], a0[1], a0[2], a0[3], ab + swz(ar,     acb + akc + ks*2)); \
            LDSM4(a1[0], a1[1], a1[2], a1[3], ab + swz(ar + 8, acb + akc + ks*2)); \
            _Pragma("unroll")                                                      \
            for (int jj = 0; jj < 2; jj++) {                                       \
                uint32_t b0, b1, b2, b3;                                           \
                LDSM4(b0, b1, b2, b3, bb + swz(nr + jj * 8, ncb + ks * 2));        \
                MMA(cc[0][jj * 2], a0, b0, b1);                                    \
                MMA(cc[0][jj * 2 + 1], a0, b2, b3);                                \
                MMA(cc[1][jj * 2], a1, b0, b1);                                    \
                MMA(cc[1][jj * 2 + 1], a1, b2, b3);                                \
            }                                                                      \
        }                                                                          \
    } while (0)

__global__ void __launch_bounds__(256, 3) outproj_tc(const float* __restrict__ bias,
                                                     const float* __restrict__ resid,
                                                     float* __restrict__ out) {
    extern __shared__ __align__(128) char arena[];
    const uint32_t base = smem_u32(arena);

    const int tid = threadIdx.x, lane = tid & 31, w = tid >> 5;
    const int wm = (w >> 1) * 32, wn = (w & 1) * 32;
    const int m0 = blockIdx.x * 128, n0 = blockIdx.y * 64;

    const int arow = tid >> 1, apart = tid & 1;
    const uint32_t adst0 = swz(arow >> 1, (arow & 1) * 4 + apart * 2);
    const uint32_t adst1 = swz(arow >> 1, (arow & 1) * 4 + apart * 2 + 1);
    const int bn = tid >> 2, bkc = tid & 3;
    const uint32_t bdst = swz(bn >> 1, (bn & 1) * 4 + bkc);

    const int b_ = m0 >> 12;
    const int s_arow = (m0 + arow) & (SS - 1);

#define OUT_A(c) (g_ob + ((size_t)(b_ * HH + ((c) >> 1)) * SS + s_arow) * DHH + ((c) & 1) * 32 + apart * 16)
#define OUT_B(c) (wob + (size_t)(n0 + bn) * CC + (c) * 32 + bkc * 8)

    FRAG_SETUP();

    float cc[2][4][4];
#pragma unroll
    for (int mi = 0; mi < 2; mi++)
#pragma unroll
        for (int nc = 0; nc < 4; nc++)
#pragma unroll
            for (int q = 0; q < 4; q++) cc[mi][nc][q] = 0.f;

    V4_PF(OUT_A(0), OUT_B(0), 0);
    V4_PF(OUT_A(1), OUT_B(1), 1);
    V4_PF(OUT_A(2), OUT_B(2), 2);
    {
        int st0 = 0;
        for (int sc = 0; sc < 10; sc++) {
            if (sc < 9) CPW1(); else CPW0();
            __syncthreads();
            int pf0 = st0 + 3; if (pf0 >= 5) pf0 -= 5;
            int pf1 = st0 + 4; if (pf1 >= 5) pf1 -= 5;
            if (sc <= 8) V4_PF(OUT_A(2 * sc + 3), OUT_B(2 * sc + 3), pf0);
            if (sc <= 7) V4_PF(OUT_A(2 * sc + 4), OUT_B(2 * sc + 4), pf1);
            int st1 = st0 + 1; if (st1 >= 5) st1 -= 5;
            V4_CONSUME(st0);
            V4_CONSUME(st1);
            st0 += 2; if (st0 >= 5) st0 -= 5;
        }
    }
#undef OUT_A
#undef OUT_B

    const int g = lane >> 2, c2 = (lane & 3) * 2;
#pragma unroll
    for (int mi = 0; mi < 2; mi++) {
        int r_lo = m0 + wm + mi * 16 + g, r_hi = r_lo + 8;
#pragma unroll
        for (int nc = 0; nc < 4; nc++) {
            int col = n0 + wn + nc * 8 + c2;
            float2 bv = *(const float2*)(bias + col);
            float2 rl = *(const float2*)(resid + (size_t)r_lo * CC + col);
            float2 rh = *(const float2*)(resid + (size_t)r_hi * CC + col);
            float2 ol, oh;
            ol.x = cc[mi][nc][0] + bv.x + rl.x; ol.y = cc[mi][nc][1] + bv.y + rl.y;
            oh.x = cc[mi][nc][2] + bv.x + rh.x; oh.y = cc[mi][nc][3] + bv.y + rh.y;
            *(float2*)(out + (size_t)r_lo * CC + col) = ol;
            *(float2*)(out + (size_t)r_hi * CC + col) = oh;
        }
    }
}

extern "C" void kernel_launch(void* const* d_in, const int* in_sizes, int n_in,
                              void* d_out, int out_size) {
    const float* hs    = (const float*)d_in[0];
    const float* Wq    = (const float*)d_in[1];
    const float* Wk    = (const float*)d_in[2];
    const float* Wv    = (const float*)d_in[3];
    const float* Wo    = (const float*)d_in[4];
    const float* b_out = (const float*)d_in[5];
    float* out = (float*)d_out;

    const float qscale = 0.125f * 1.44269504088896340736f;

    cudaFuncSetAttribute(projqkv_tc, cudaFuncAttributeMaxDynamicSharedMemorySize, 102400);
    cudaFuncSetAttribute(outproj_tc, cudaFuncAttributeMaxDynamicSharedMemorySize, 61440);
    cudaFuncSetAttribute(attn_tc, cudaFuncAttributeMaxDynamicSharedMemorySize, 98304);

    cvt_all<<<(CVT_Q + 255) / 256, 256>>>(hs, Wq, Wk, Wv, Wo, qscale);

    projqkv_tc<<<dim3(BB * SS / 128, HH), 256, 102400>>>();
    attn_tc<<<dim3(SS / 128, BH, 2), 256, 98304>>>();
    const int nc8 = NOB / 8;
    combine_k<<<(nc8 + 255) / 256, 256>>>(nc8);
    outproj_tc<<<dim3(BB * SS / 128, HH), 256, 61440>>>(b_out, hs, out);
}

// round 15
// speedup vs baseline: 1.0266x; 1.0266x over previous
#include <cuda_runtime.h>
#include <cuda_bf16.h>
#include <cstdint>

#define BB  2
#define SS  4096
#define CC  640
#define HH  10
#define DHH 64
#define BH  (BB*HH)
#define NHS4 (BB*SS*CC/4)
#define NW4  (CC*CC/4)
#define NOB  (BH*SS*DHH)

// ---------------- scratch (no allocations allowed) ----------------
__device__ __align__(16) __nv_bfloat16 hsb[BB*SS*CC];
__device__ __align__(16) __nv_bfloat16 wqb[CC*CC];      // Wq * qscale
__device__ __align__(16) __nv_bfloat16 wkb[CC*CC];
__device__ __align__(16) __nv_bfloat16 wvb[CC*CC];
__device__ __align__(16) __nv_bfloat16 wob[CC*CC];
__device__ __align__(16) __nv_bfloat16 g_qb[NOB];       // Q bf16 [bh][s][d] (prescaled)
__device__ __align__(16) __nv_bfloat16 g_kb[NOB];       // K bf16 [bh][s][d]
__device__ __align__(16) __nv_bfloat16 g_vt[NOB];       // V^T bf16 [bh][d][s]
__device__ __align__(16) __nv_bfloat16 g_ob[NOB];       // attn out bf16 [bh][s][d]
__device__ __align__(16) __nv_bfloat16 g_po[2][NOB];    // split-K partial O (bf16, unnorm)
__device__ __align__(16) float g_pl[2][BH*SS];          // split-K partial row sums

// ---------------- helpers ----------------
__device__ __forceinline__ uint32_t smem_u32(const void* p) {
    uint32_t a;
    asm("{ .reg .u64 t; cvta.to.shared.u64 t, %1; cvt.u32.u64 %0, t; }" : "=r"(a) : "l"(p));
    return a;
}
__device__ __forceinline__ uint32_t swz(uint32_t r, uint32_t cb) {
    return r * 128u + ((cb ^ (r & 7u)) << 4);
}
__device__ __forceinline__ uint32_t pkbf(float a, float b) {
    __nv_bfloat162 h = __float22bfloat162_rn(make_float2(a, b));
    return *(uint32_t*)&h;
}
__device__ __forceinline__ float ex2(float x) {
    float y;
    asm("ex2.approx.ftz.f32 %0, %1;" : "=f"(y) : "f"(x));
    return y;
}

#define LDSM4(R0, R1, R2, R3, A)                                                   \
    asm volatile("ldmatrix.sync.aligned.m8n8.x4.shared.b16 {%0,%1,%2,%3}, [%4];"   \
                 : "=r"(R0), "=r"(R1), "=r"(R2), "=r"(R3) : "r"(A))

#define MMA(C, A, B0, B1)                                                          \
    asm volatile("mma.sync.aligned.m16n8k16.row.col.f32.bf16.bf16.f32 "            \
                 "{%0,%1,%2,%3}, {%4,%5,%6,%7}, {%8,%9}, {%0,%1,%2,%3};"           \
                 : "+f"((C)[0]), "+f"((C)[1]), "+f"((C)[2]), "+f"((C)[3])          \
                 : "r"((A)[0]), "r"((A)[1]), "r"((A)[2]), "r"((A)[3]),             \
                   "r"(B0), "r"(B1))

#define CPA(D, S)  asm volatile("cp.async.cg.shared.global [%0], [%1], 16;" :: "r"(D), "l"(S))
#define CPC()      asm volatile("cp.async.commit_group;" ::: "memory")
#define CPW0()     asm volatile("cp.async.wait_group 0;" ::: "memory")
#define CPW1()     asm volatile("cp.async.wait_group 1;" ::: "memory")

// ---------------- fp32 -> bf16 convert (MLP=4) ----------------
#define CVT_TOT (NHS4 + 4 * NW4)
#define CVT_Q   (CVT_TOT / 4)
__global__ void __launch_bounds__(256) cvt_all(const float* __restrict__ hs,
                                               const float* __restrict__ Wq,
                                               const float* __restrict__ Wk,
                                               const float* __restrict__ Wv,
                                               const float* __restrict__ Wo,
                                               float qscale) {
    int i0 = blockIdx.x * 256 + threadIdx.x;
    if (i0 >= CVT_Q) return;
#pragma unroll
    for (int q = 0; q < 4; q++) {
        int i = i0 + q * CVT_Q;
        const float* src;
        __nv_bfloat16* dst;
        float sc = 1.f;
        int off;
        if (i < NHS4) {
            src = hs; dst = hsb; off = i;
        } else {
            int j = i - NHS4;
            int sel = j / NW4;
            off = j - sel * NW4;
            src = (sel == 0) ? Wq : (sel == 1) ? Wk : (sel == 2) ? Wv : Wo;
            dst = (sel == 0) ? wqb : (sel == 1) ? wkb : (sel == 2) ? wvb : wob;
            if (sel == 0) sc = qscale;
        }
        float4 v = ((const float4*)src)[off];
        uint2 u;
        u.x = pkbf(v.x * sc, v.y * sc);
        u.y = pkbf(v.z * sc, v.w * sc);
        ((uint2*)dst)[off] = u;
    }
}

// ============================================================================
// GEMM v4 (race-free, round-13 proven): 128m x 64n, BK=32, 5 stages,
// 2 chunks per barrier. wait -> barrier -> prefetch -> consume.
// ============================================================================

#define V4_PF(ASRC, BSRC, stg) do {                                               \
        uint32_t ao = base + (stg) * 12288, bo = ao + 8192;                        \
        CPA(ao + adst0, (ASRC));                                                   \
        CPA(ao + adst1, (ASRC) + 8);                                               \
        CPA(bo + bdst, (BSRC));                                                    \
        CPC();                                                                     \
    } while (0)

#define V4_CONSUME(STG) do {                                                       \
        uint32_t ab = base + (STG) * 12288, bb = ab + 8192;                        \
        _Pragma("unroll")                                                          \
        for (int ks = 0; ks < 2; ks++) {                                           \
            uint32_t a0[4], a1[4];                                                 \
            LDSM4(a0[0], a0[1], a0[2], a0[3], ab + swz(ar,     acb + akc + ks*2)); \
            LDSM4(a1[0], a1[1], a1[2], a1[3], ab + swz(ar + 8, acb + akc + ks*2)); \
            _Pragma("unroll")                                                      \
            for (int jj = 0; jj < 2; jj++) {                                       \
                uint32_t b0, b1, b2, b3;                                           \
                LDSM4(b0, b1, b2, b3, bb + swz(nr + jj * 8, ncb + ks * 2));        \
                MMA(cc[0][jj * 2], a0, b0, b1);                                    \
                MMA(cc[0][jj * 2 + 1], a0, b2, b3);                                \
                MMA(cc[1][jj * 2], a1, b0, b1);                                    \
                MMA(cc[1][jj * 2 + 1], a1, b2, b3);                                \
            }                                                                      \
        }                                                                          \
    } while (0)

#define FRAG_SETUP()                                                               \
    const uint32_t ar  = (uint32_t)((wm >> 1) + ((lane & 15) >> 1));               \
    const uint32_t acb = (uint32_t)((lane & 1) * 4);                               \
    const uint32_t akc = (uint32_t)(lane >> 4);                                    \
    const uint32_t nlb = (uint32_t)(wn + (lane & 7) + ((lane >> 4) << 3));         \
    const uint32_t nr  = nlb >> 1;                                                 \
    const uint32_t ncb = ((nlb & 1) << 2) + ((lane >> 3) & 1)

#define V4_LOOP(A_OF, B_OF)                                                        \
    V4_PF(A_OF(0), B_OF(0), 0);                                                    \
    V4_PF(A_OF(1), B_OF(1), 1);                                                    \
    V4_PF(A_OF(2), B_OF(2), 2);                                                    \
    {                                                                              \
        int st0 = 0;                                                               \
        for (int sc = 0; sc < 10; sc++) {                                          \
            if (sc < 9) CPW1(); else CPW0();                                       \
            __syncthreads();                                                       \
            int pf0 = st0 + 3; if (pf0 >= 5) pf0 -= 5;                             \
            int pf1 = st0 + 4; if (pf1 >= 5) pf1 -= 5;                             \
            if (sc <= 8) V4_PF(A_OF(2 * sc + 3), B_OF(2 * sc + 3), pf0);           \
            if (sc <= 7) V4_PF(A_OF(2 * sc + 4), B_OF(2 * sc + 4), pf1);           \
            int st1 = st0 + 1; if (st1 >= 5) st1 -= 5;                             \
            V4_CONSUME(st0);                                                       \
            V4_CONSUME(st1);                                                       \
            st0 += 2; if (st0 >= 5) st0 -= 5;                                      \
        }                                                                          \
    }

// ---------------- QKV projection: grid (64, 10, 3) ----------------
__global__ void __launch_bounds__(256, 3) proj_tc() {
    extern __shared__ __align__(128) char arena[];
    const uint32_t base = smem_u32(arena);

    const int tid = threadIdx.x, lane = tid & 31, w = tid >> 5;
    const int wm = (w >> 1) * 32, wn = (w & 1) * 32;
    const int sel = blockIdx.z, h = blockIdx.y, m0 = blockIdx.x * 128;
    const int n0 = h * 64;
    const __nv_bfloat16* W = (sel == 0) ? wqb : (sel == 1) ? wkb : wvb;

    const int arow = tid >> 1, apart = tid & 1;
    const uint32_t adst0 = swz(arow >> 1, (arow & 1) * 4 + apart * 2);
    const uint32_t adst1 = swz(arow >> 1, (arow & 1) * 4 + apart * 2 + 1);
    const int bn = tid >> 2, bkc = tid & 3;
    const uint32_t bdst = swz(bn >> 1, (bn & 1) * 4 + bkc);

#define PROJ_A(c) (hsb + (size_t)(m0 + arow) * CC + (c) * 32 + apart * 16)
#define PROJ_B(c) (W   + (size_t)(n0 + bn) * CC + (c) * 32 + bkc * 8)

    FRAG_SETUP();

    float cc[2][4][4];
#pragma unroll
    for (int mi = 0; mi < 2; mi++)
#pragma unroll
        for (int nc = 0; nc < 4; nc++)
#pragma unroll
            for (int q = 0; q < 4; q++) cc[mi][nc][q] = 0.f;

    V4_LOOP(PROJ_A, PROJ_B)
#undef PROJ_A
#undef PROJ_B

    const int g = lane >> 2, c2 = (lane & 3) * 2;
    const int b_ = m0 >> 12;
    if (sel == 2) {
        // staged transpose: stt[d 64][m 128] pitch 136 elems
        __syncthreads();
        __nv_bfloat16* stt = (__nv_bfloat16*)arena;
#pragma unroll
        for (int mi = 0; mi < 2; mi++) {
            int ml = wm + mi * 16 + g, mh = ml + 8;
#pragma unroll
            for (int nc = 0; nc < 4; nc++) {
                int d = wn + nc * 8 + c2;
                stt[d * 136 + ml]       = __float2bfloat16(cc[mi][nc][0]);
                stt[(d + 1) * 136 + ml] = __float2bfloat16(cc[mi][nc][1]);
                stt[d * 136 + mh]       = __float2bfloat16(cc[mi][nc][2]);
                stt[(d + 1) * 136 + mh] = __float2bfloat16(cc[mi][nc][3]);
            }
        }
        __syncthreads();
        const int row = tid >> 2, part = tid & 3;
        const int s_base = m0 & (SS - 1);
        __nv_bfloat16* dst = g_vt + ((size_t)(b_ * HH + h) * DHH + row) * SS + s_base + part * 32;
        const uint4* srcp = (const uint4*)(stt + row * 136 + part * 32);
#pragma unroll
        for (int i = 0; i < 4; i++)
            ((uint4*)dst)[i] = srcp[i];
    } else {
        __nv_bfloat16* dst = (sel == 0) ? g_qb : g_kb;
        const size_t rowbase = (size_t)(b_ * HH + h) * SS;
#pragma unroll
        for (int mi = 0; mi < 2; mi++) {
            int r_lo = m0 + wm + mi * 16 + g, r_hi = r_lo + 8;
            __nv_bfloat16* plo = dst + (rowbase + (r_lo & (SS - 1))) * DHH;
            __nv_bfloat16* phi = dst + (rowbase + (r_hi & (SS - 1))) * DHH;
#pragma unroll
            for (int nc = 0; nc < 4; nc++) {
                int d = wn + nc * 8 + c2;
                *(uint32_t*)(plo + d) = pkbf(cc[mi][nc][0], cc[mi][nc][1]);
                *(uint32_t*)(phi + d) = pkbf(cc[mi][nc][2], cc[mi][nc][3]);
            }
        }
    }
}

// ---------------- flash attention: bf16, split-K, 3-stage ring --------------
// grid (32, 20, 2), 256 threads. 3 stages x 32768B = 98304B dynamic smem.
// Deferred softmax reduction: quad-shuffles once after the loop.
__global__ void __launch_bounds__(256, 2) attn_tc() {
    extern __shared__ __align__(128) char arena[];
    const uint32_t base = smem_u32(arena);

    const int tid = threadIdx.x, lane = tid & 31, w = tid >> 5;
    const int s0 = blockIdx.x * 128, bh = blockIdx.y, z = blockIdx.z;
    const int k_base = z * (SS / 2);
    const __nv_bfloat16* Qg = g_qb + (size_t)bh * SS * DHH;
    const __nv_bfloat16* Kg = g_kb + (size_t)bh * SS * DHH;
    const __nv_bfloat16* Vg = g_vt + (size_t)bh * DHH * SS;

    // stage Q bf16 tile [128][64] into stage-2 region (offset 65536).
    // PFS(2) first overwrites stage 2 at T=0 AFTER the loop-top barrier,
    // which orders the Q-fragment reads below.
    {
        int row = tid >> 1, half = tid & 1;
        const uint4* src = (const uint4*)(Qg + (size_t)(s0 + row) * DHH + half * 32);
#pragma unroll
        for (int i = 0; i < 4; i++)
            *(uint4*)(arena + 65536 + swz(row, half * 4 + i)) = src[i];
    }
    __syncthreads();

    uint32_t aq[4][4];
    {
        uint32_t r = w * 16 + (lane & 7) + (lane & 8);
#pragma unroll
        for (int ks = 0; ks < 4; ks++) {
            uint32_t cb = ks * 2 + (lane >> 4);
            LDSM4(aq[ks][0], aq[ks][1], aq[ks][2], aq[ks][3], base + 65536 + swz(r, cb));
        }
    }

    const int prow = tid >> 2, pcb = (tid & 3) * 2;
#define PFS(T, stg) do {                                                           \
        uint32_t so = base + (stg) * 32768;                                        \
        int j0 = k_base + (T) * 128;                                               \
        _Pragma("unroll") for (int sub = 0; sub < 2; sub++) {                      \
            uint32_t ko = so + sub * 16384, vo = ko + 8192;                        \
            const __nv_bfloat16* ks_ = Kg + (size_t)(j0 + sub * 64 + prow) * DHH;  \
            const __nv_bfloat16* vs_ = Vg + (size_t)prow * SS + j0 + sub * 64;     \
            _Pragma("unroll") for (int i = 0; i < 2; i++) {                        \
                CPA(ko + swz(prow, pcb + i), ks_ + (pcb + i) * 8);                 \
                CPA(vo + swz(prow, pcb + i), vs_ + (pcb + i) * 8);                 \
            }                                                                      \
        }                                                                          \
        CPC();                                                                     \
    } while (0)

    PFS(0, 0);
    PFS(1, 1);

    float co[8][4];
#pragma unroll
    for (int j = 0; j < 8; j++)
#pragma unroll
        for (int q = 0; q < 4; q++) co[j][q] = 0.f;
    float lacc_lo = 0.f, lacc_hi = 0.f;   // per-thread partials (reduced post-loop)

    const uint32_t brow = (lane & 7) + ((lane >> 4) << 3);
    const uint32_t bsel = (lane >> 3) & 1;

    int st = 0, pfst = 2;
    for (int T = 0; T < 16; T++) {
        if (T < 15) CPW1(); else CPW0();   // group T, issued 2 iters ago
        __syncthreads();                    // publish stage st; readers of pfst done
        if (T < 14) PFS(T + 2, pfst);
        const uint32_t stg = base + st * 32768;
        st = (st == 2) ? 0 : st + 1;
        pfst = (pfst == 2) ? 0 : pfst + 1;

#pragma unroll
        for (int sub = 0; sub < 2; sub++) {
            uint32_t kb = stg + sub * 16384, vb = kb + 8192;

            // S = Q K^T
            float cs[8][4];
#pragma unroll
            for (int j = 0; j < 8; j++)
#pragma unroll
                for (int q = 0; q < 4; q++) cs[j][q] = 0.f;
#pragma unroll
            for (int ks = 0; ks < 4; ks++) {
                uint32_t bc = ks * 2 + bsel;
#pragma unroll
                for (int j = 0; j < 8; j += 2) {
                    uint32_t b0, b1, b2, b3;
                    LDSM4(b0, b1, b2, b3, kb + swz(j * 8 + brow, bc));
                    MMA(cs[j], aq[ks], b0, b1);
                    MMA(cs[j + 1], aq[ks], b2, b3);
                }
            }

            // softmax: exp only; quad reduction deferred
            uint32_t pa[4][4];
#pragma unroll
            for (int j = 0; j < 8; j++) {
                float e0 = ex2(cs[j][0]), e1 = ex2(cs[j][1]);
                float e2 = ex2(cs[j][2]), e3 = ex2(cs[j][3]);
                lacc_lo += e0 + e1; lacc_hi += e2 + e3;
                pa[j >> 1][(j & 1) * 2 + 0] = pkbf(e0, e1);
                pa[j >> 1][(j & 1) * 2 + 1] = pkbf(e2, e3);
            }

            // O += P V
#pragma unroll
            for (int kc = 0; kc < 4; kc++) {
                uint32_t bc = kc * 2 + bsel;
#pragma unroll
                for (int j = 0; j < 8; j += 2) {
                    uint32_t b0, b1, b2, b3;
                    LDSM4(b0, b1, b2, b3, vb + swz(j * 8 + brow, bc));
                    MMA(co[j], pa[kc], b0, b1);
                    MMA(co[j + 1], pa[kc], b2, b3);
                }
            }
        }
    }
#undef PFS

    // final quad reduction (linear, order-independent up to fp rounding)
    lacc_lo += __shfl_xor_sync(0xffffffffu, lacc_lo, 1);
    lacc_lo += __shfl_xor_sync(0xffffffffu, lacc_lo, 2);
    lacc_hi += __shfl_xor_sync(0xffffffffu, lacc_hi, 1);
    lacc_hi += __shfl_xor_sync(0xffffffffu, lacc_hi, 2);

    // epilogue: store unnormalized bf16 partials + fp32 row sums
    const int g = lane >> 2, c2 = (lane & 3) * 2;
    const int r_lo = s0 + w * 16 + g, r_hi = r_lo + 8;
    __nv_bfloat16* plo = g_po[z] + ((size_t)bh * SS + r_lo) * DHH;
    __nv_bfloat16* phi = g_po[z] + ((size_t)bh * SS + r_hi) * DHH;
#pragma unroll
    for (int j = 0; j < 8; j++) {
        int col = j * 8 + c2;
        *(uint32_t*)(plo + col) = pkbf(co[j][0], co[j][1]);
        *(uint32_t*)(phi + col) = pkbf(co[j][2], co[j][3]);
    }
    g_pl[z][(size_t)bh * SS + r_lo] = lacc_lo;
    g_pl[z][(size_t)bh * SS + r_hi] = lacc_hi;
}

// ---------------- split-K combine: g_ob = bf16((po0+po1)/(l0+l1)) ----------
__global__ void __launch_bounds__(256) combine_k(int n8) {
    int i = blockIdx.x * 256 + threadIdx.x;
    if (i >= n8) return;
    int row = i >> 3;
    float l = g_pl[0][row] + g_pl[1][row];
    float inv = 1.f / l;
    uint4 a = ((const uint4*)g_po[0])[i];
    uint4 b = ((const uint4*)g_po[1])[i];
    uint4 o;
    const uint32_t* ap = &a.x;
    const uint32_t* bp = &b.x;
    uint32_t* op = &o.x;
#pragma unroll
    for (int q = 0; q < 4; q++) {
        float2 fa = __bfloat1622float2(*(const __nv_bfloat162*)&ap[q]);
        float2 fb = __bfloat1622float2(*(const __nv_bfloat162*)&bp[q]);
        op[q] = pkbf((fa.x + fb.x) * inv, (fa.y + fb.y) * inv);
    }
    ((uint4*)g_ob)[i] = o;
}

// ---------------- output projection + bias + residual (GEMM v4) ------------
// grid (64, 10)
__global__ void __launch_bounds__(256, 3) outproj_tc(const float* __restrict__ bias,
                                                     const float* __restrict__ resid,
                                                     float* __restrict__ out) {
    extern __shared__ __align__(128) char arena[];
    const uint32_t base = smem_u32(arena);

    const int tid = threadIdx.x, lane = tid & 31, w = tid >> 5;
    const int wm = (w >> 1) * 32, wn = (w & 1) * 32;
    const int m0 = blockIdx.x * 128, n0 = blockIdx.y * 64;

    const int arow = tid >> 1, apart = tid & 1;
    const uint32_t adst0 = swz(arow >> 1, (arow & 1) * 4 + apart * 2);
    const uint32_t adst1 = swz(arow >> 1, (arow & 1) * 4 + apart * 2 + 1);
    const int bn = tid >> 2, bkc = tid & 3;
    const uint32_t bdst = swz(bn >> 1, (bn & 1) * 4 + bkc);

    const int b_ = m0 >> 12;
    const int s_arow = (m0 + arow) & (SS - 1);

#define OUT_A(c) (g_ob + ((size_t)(b_ * HH + ((c) >> 1)) * SS + s_arow) * DHH + ((c) & 1) * 32 + apart * 16)
#define OUT_B(c) (wob + (size_t)(n0 + bn) * CC + (c) * 32 + bkc * 8)

    FRAG_SETUP();

    float cc[2][4][4];
#pragma unroll
    for (int mi = 0; mi < 2; mi++)
#pragma unroll
        for (int nc = 0; nc < 4; nc++)
#pragma unroll
            for (int q = 0; q < 4; q++) cc[mi][nc][q] = 0.f;

    V4_LOOP(OUT_A, OUT_B)
#undef OUT_A
#undef OUT_B

    const int g = lane >> 2, c2 = (lane & 3) * 2;
#pragma unroll
    for (int mi = 0; mi < 2; mi++) {
        int r_lo = m0 + wm + mi * 16 + g, r_hi = r_lo + 8;
#pragma unroll
        for (int nc = 0; nc < 4; nc++) {
            int col = n0 + wn + nc * 8 + c2;
            float2 bv = *(const float2*)(bias + col);
            float2 rl = *(const float2*)(resid + (size_t)r_lo * CC + col);
            float2 rh = *(const float2*)(resid + (size_t)r_hi * CC + col);
            float2 ol, oh;
            ol.x = cc[mi][nc][0] + bv.x + rl.x; ol.y = cc[mi][nc][1] + bv.y + rl.y;
            oh.x = cc[mi][nc][2] + bv.x + rh.x; oh.y = cc[mi][nc][3] + bv.y + rh.y;
            *(float2*)(out + (size_t)r_lo * CC + col) = ol;
            *(float2*)(out + (size_t)r_hi * CC + col) = oh;
        }
    }
}

extern "C" void kernel_launch(void* const* d_in, const int* in_sizes, int n_in,
                              void* d_out, int out_size) {
    const float* hs    = (const float*)d_in[0];
    const float* Wq    = (const float*)d_in[1];
    const float* Wk    = (const float*)d_in[2];
    const float* Wv    = (const float*)d_in[3];
    const float* Wo    = (const float*)d_in[4];
    const float* b_out = (const float*)d_in[5];
    float* out = (float*)d_out;

    const float qscale = 0.125f * 1.44269504088896340736f;  // 1/sqrt(64) * log2(e)

    cudaFuncSetAttribute(proj_tc, cudaFuncAttributeMaxDynamicSharedMemorySize, 61440);
    cudaFuncSetAttribute(outproj_tc, cudaFuncAttributeMaxDynamicSharedMemorySize, 61440);
    cudaFuncSetAttribute(attn_tc, cudaFuncAttributeMaxDynamicSharedMemorySize, 98304);

    cvt_all<<<(CVT_Q + 255) / 256, 256>>>(hs, Wq, Wk, Wv, Wo, qscale);

    proj_tc<<<dim3(BB * SS / 128, HH, 3), 256, 61440>>>();
    attn_tc<<<dim3(SS / 128, BH, 2), 256, 98304>>>();
    const int nc8 = NOB / 8;
    combine_k<<<(nc8 + 255) / 256, 256>>>(nc8);
    outproj_tc<<<dim3(BB * SS / 128, HH), 256, 61440>>>(b_out, hs, out);
}

// round 16
// speedup vs baseline: 1.0338x; 1.0070x over previous
#include <cuda_runtime.h>
#include <cuda_bf16.h>
#include <cstdint>

#define BB  2
#define SS  4096
#define CC  640
#define HH  10
#define DHH 64
#define BH  (BB*HH)
#define NHS4 (BB*SS*CC/4)
#define NW4  (CC*CC/4)
#define NOB  (BH*SS*DHH)
#define NSPLIT 4

// ---------------- scratch (no allocations allowed) ----------------
__device__ __align__(16) __nv_bfloat16 hsb[BB*SS*CC];
__device__ __align__(16) __nv_bfloat16 wqb[CC*CC];      // Wq * qscale
__device__ __align__(16) __nv_bfloat16 wkb[CC*CC];
__device__ __align__(16) __nv_bfloat16 wvb[CC*CC];
__device__ __align__(16) __nv_bfloat16 wob[CC*CC];
__device__ __align__(16) __nv_bfloat16 g_qb[NOB];       // Q bf16 [bh][s][d] (prescaled)
__device__ __align__(16) __nv_bfloat16 g_kb[NOB];       // K bf16 [bh][s][d]
__device__ __align__(16) __nv_bfloat16 g_vt[NOB];       // V^T bf16 [bh][d][s]
__device__ __align__(16) __nv_bfloat16 g_ob[NOB];       // attn out bf16 [bh][s][d]
__device__ __align__(16) __nv_bfloat16 g_po[NSPLIT][NOB];  // split-K partial O (bf16)
__device__ __align__(16) float g_pl[NSPLIT][BH*SS];        // split-K partial row sums

// ---------------- helpers ----------------
__device__ __forceinline__ uint32_t smem_u32(const void* p) {
    uint32_t a;
    asm("{ .reg .u64 t; cvta.to.shared.u64 t, %1; cvt.u32.u64 %0, t; }" : "=r"(a) : "l"(p));
    return a;
}
__device__ __forceinline__ uint32_t swz(uint32_t r, uint32_t cb) {
    return r * 128u + ((cb ^ (r & 7u)) << 4);
}
__device__ __forceinline__ uint32_t pkbf(float a, float b) {
    __nv_bfloat162 h = __float22bfloat162_rn(make_float2(a, b));
    return *(uint32_t*)&h;
}
__device__ __forceinline__ float ex2(float x) {
    float y;
    asm("ex2.approx.ftz.f32 %0, %1;" : "=f"(y) : "f"(x));
    return y;
}

#define LDSM4(R0, R1, R2, R3, A)                                                   \
    asm volatile("ldmatrix.sync.aligned.m8n8.x4.shared.b16 {%0,%1,%2,%3}, [%4];"   \
                 : "=r"(R0), "=r"(R1), "=r"(R2), "=r"(R3) : "r"(A))

#define MMA(C, A, B0, B1)                                                          \
    asm volatile("mma.sync.aligned.m16n8k16.row.col.f32.bf16.bf16.f32 "            \
                 "{%0,%1,%2,%3}, {%4,%5,%6,%7}, {%8,%9}, {%0,%1,%2,%3};"           \
                 : "+f"((C)[0]), "+f"((C)[1]), "+f"((C)[2]), "+f"((C)[3])          \
                 : "r"((A)[0]), "r"((A)[1]), "r"((A)[2]), "r"((A)[3]),             \
                   "r"(B0), "r"(B1))

#define CPA(D, S)  asm volatile("cp.async.cg.shared.global [%0], [%1], 16;" :: "r"(D), "l"(S))
#define CPC()      asm volatile("cp.async.commit_group;" ::: "memory")
#define CPW0()     asm volatile("cp.async.wait_group 0;" ::: "memory")
#define CPW1()     asm volatile("cp.async.wait_group 1;" ::: "memory")

// ---------------- fp32 -> bf16 convert (MLP=4) ----------------
#define CVT_TOT (NHS4 + 4 * NW4)
#define CVT_Q   (CVT_TOT / 4)
__global__ void __launch_bounds__(256) cvt_all(const float* __restrict__ hs,
                                               const float* __restrict__ Wq,
                                               const float* __restrict__ Wk,
                                               const float* __restrict__ Wv,
                                               const float* __restrict__ Wo,
                                               float qscale) {
    int i0 = blockIdx.x * 256 + threadIdx.x;
    if (i0 >= CVT_Q) return;
#pragma unroll
    for (int q = 0; q < 4; q++) {
        int i = i0 + q * CVT_Q;
        const float* src;
        __nv_bfloat16* dst;
        float sc = 1.f;
        int off;
        if (i < NHS4) {
            src = hs; dst = hsb; off = i;
        } else {
            int j = i - NHS4;
            int sel = j / NW4;
            off = j - sel * NW4;
            src = (sel == 0) ? Wq : (sel == 1) ? Wk : (sel == 2) ? Wv : Wo;
            dst = (sel == 0) ? wqb : (sel == 1) ? wkb : (sel == 2) ? wvb : wob;
            if (sel == 0) sc = qscale;
        }
        float4 v = ((const float4*)src)[off];
        uint2 u;
        u.x = pkbf(v.x * sc, v.y * sc);
        u.y = pkbf(v.z * sc, v.w * sc);
        ((uint2*)dst)[off] = u;
    }
}

// ============================================================================
// GEMM v4 (race-free): 128m x 64n, BK=32, 5 stages, 2 chunks per barrier.
// ============================================================================

#define V4_PF(ASRC, BSRC, stg) do {                                               \
        uint32_t ao = base + (stg) * 12288, bo = ao + 8192;                        \
        CPA(ao + adst0, (ASRC));                                                   \
        CPA(ao + adst1, (ASRC) + 8);                                               \
        CPA(bo + bdst, (BSRC));                                                    \
        CPC();                                                                     \
    } while (0)

#define V4_CONSUME(STG) do {                                                       \
        uint32_t ab = base + (STG) * 12288, bb = ab + 8192;                        \
        _Pragma("unroll")                                                          \
        for (int ks = 0; ks < 2; ks++) {                                           \
            uint32_t a0[4], a1[4];                                                 \
            LDSM4(a0[0], a0[1], a0[2], a0[3], ab + swz(ar,     acb + akc + ks*2)); \
            LDSM4(a1[0], a1[1], a1[2], a1[3], ab + swz(ar + 8, acb + akc + ks*2)); \
            _Pragma("unroll")                                                      \
            for (int jj = 0; jj < 2; jj++) {                                       \
                uint32_t b0, b1, b2, b3;                                           \
                LDSM4(b0, b1, b2, b3, bb + swz(nr + jj * 8, ncb + ks * 2));        \
                MMA(cc[0][jj * 2], a0, b0, b1);                                    \
                MMA(cc[0][jj * 2 + 1], a0, b2, b3);                                \
                MMA(cc[1][jj * 2], a1, b0, b1);                                    \
                MMA(cc[1][jj * 2 + 1], a1, b2, b3);                                \
            }                                                                      \
        }                                                                          \
    } while (0)

#define FRAG_SETUP()                                                               \
    const uint32_t ar  = (uint32_t)((wm >> 1) + ((lane & 15) >> 1));               \
    const uint32_t acb = (uint32_t)((lane & 1) * 4);                               \
    const uint32_t akc = (uint32_t)(lane >> 4);                                    \
    const uint32_t nlb = (uint32_t)(wn + (lane & 7) + ((lane >> 4) << 3));         \
    const uint32_t nr  = nlb >> 1;                                                 \
    const uint32_t ncb = ((nlb & 1) << 2) + ((lane >> 3) & 1)

#define V4_LOOP(A_OF, B_OF)                                                        \
    V4_PF(A_OF(0), B_OF(0), 0);                                                    \
    V4_PF(A_OF(1), B_OF(1), 1);                                                    \
    V4_PF(A_OF(2), B_OF(2), 2);                                                    \
    {                                                                              \
        int st0 = 0;                                                               \
        for (int sc = 0; sc < 10; sc++) {                                          \
            if (sc < 9) CPW1(); else CPW0();                                       \
            __syncthreads();                                                       \
            int pf0 = st0 + 3; if (pf0 >= 5) pf0 -= 5;                             \
            int pf1 = st0 + 4; if (pf1 >= 5) pf1 -= 5;                             \
            if (sc <= 8) V4_PF(A_OF(2 * sc + 3), B_OF(2 * sc + 3), pf0);           \
            if (sc <= 7) V4_PF(A_OF(2 * sc + 4), B_OF(2 * sc + 4), pf1);           \
            int st1 = st0 + 1; if (st1 >= 5) st1 -= 5;                             \
            V4_CONSUME(st0);                                                       \
            V4_CONSUME(st1);                                                       \
            st0 += 2; if (st0 >= 5) st0 -= 5;                                      \
        }                                                                          \
    }

// ---------------- QKV projection: grid (64, 10, 3) ----------------
__global__ void __launch_bounds__(256, 3) proj_tc() {
    extern __shared__ __align__(128) char arena[];
    const uint32_t base = smem_u32(arena);

    const int tid = threadIdx.x, lane = tid & 31, w = tid >> 5;
    const int wm = (w >> 1) * 32, wn = (w & 1) * 32;
    const int sel = blockIdx.z, h = blockIdx.y, m0 = blockIdx.x * 128;
    const int n0 = h * 64;
    const __nv_bfloat16* W = (sel == 0) ? wqb : (sel == 1) ? wkb : wvb;

    const int arow = tid >> 1, apart = tid & 1;
    const uint32_t adst0 = swz(arow >> 1, (arow & 1) * 4 + apart * 2);
    const uint32_t adst1 = swz(arow >> 1, (arow & 1) * 4 + apart * 2 + 1);
    const int bn = tid >> 2, bkc = tid & 3;
    const uint32_t bdst = swz(bn >> 1, (bn & 1) * 4 + bkc);

#define PROJ_A(c) (hsb + (size_t)(m0 + arow) * CC + (c) * 32 + apart * 16)
#define PROJ_B(c) (W   + (size_t)(n0 + bn) * CC + (c) * 32 + bkc * 8)

    FRAG_SETUP();

    float cc[2][4][4];
#pragma unroll
    for (int mi = 0; mi < 2; mi++)
#pragma unroll
        for (int nc = 0; nc < 4; nc++)
#pragma unroll
            for (int q = 0; q < 4; q++) cc[mi][nc][q] = 0.f;

    V4_LOOP(PROJ_A, PROJ_B)
#undef PROJ_A
#undef PROJ_B

    const int g = lane >> 2, c2 = (lane & 3) * 2;
    const int b_ = m0 >> 12;
    if (sel == 2) {
        __syncthreads();
        __nv_bfloat16* stt = (__nv_bfloat16*)arena;
#pragma unroll
        for (int mi = 0; mi < 2; mi++) {
            int ml = wm + mi * 16 + g, mh = ml + 8;
#pragma unroll
            for (int nc = 0; nc < 4; nc++) {
                int d = wn + nc * 8 + c2;
                stt[d * 136 + ml]       = __float2bfloat16(cc[mi][nc][0]);
                stt[(d + 1) * 136 + ml] = __float2bfloat16(cc[mi][nc][1]);
                stt[d * 136 + mh]       = __float2bfloat16(cc[mi][nc][2]);
                stt[(d + 1) * 136 + mh] = __float2bfloat16(cc[mi][nc][3]);
            }
        }
        __syncthreads();
        const int row = tid >> 2, part = tid & 3;
        const int s_base = m0 & (SS - 1);
        __nv_bfloat16* dst = g_vt + ((size_t)(b_ * HH + h) * DHH + row) * SS + s_base + part * 32;
        const uint4* srcp = (const uint4*)(stt + row * 136 + part * 32);
#pragma unroll
        for (int i = 0; i < 4; i++)
            ((uint4*)dst)[i] = srcp[i];
    } else {
        __nv_bfloat16* dst = (sel == 0) ? g_qb : g_kb;
        const size_t rowbase = (size_t)(b_ * HH + h) * SS;
#pragma unroll
        for (int mi = 0; mi < 2; mi++) {
            int r_lo = m0 + wm + mi * 16 + g, r_hi = r_lo + 8;
            __nv_bfloat16* plo = dst + (rowbase + (r_lo & (SS - 1))) * DHH;
            __nv_bfloat16* phi = dst + (rowbase + (r_hi & (SS - 1))) * DHH;
#pragma unroll
            for (int nc = 0; nc < 4; nc++) {
                int d = wn + nc * 8 + c2;
                *(uint32_t*)(plo + d) = pkbf(cc[mi][nc][0], cc[mi][nc][1]);
                *(uint32_t*)(phi + d) = pkbf(cc[mi][nc][2], cc[mi][nc][3]);
            }
        }
    }
}

// ---------------- flash attention: bf16, split-K=4, 3-stage ring ------------
// grid (32, 20, 4), 256 threads. Each CTA: 128 q rows x 1024 keys
// (8 supertiles of 128 keys). 3 stages x 32768B = 98304B dynamic smem.
__global__ void __launch_bounds__(256, 2) attn_tc() {
    extern __shared__ __align__(128) char arena[];
    const uint32_t base = smem_u32(arena);

    const int tid = threadIdx.x, lane = tid & 31, w = tid >> 5;
    const int s0 = blockIdx.x * 128, bh = blockIdx.y, z = blockIdx.z;
    const int k_base = z * (SS / NSPLIT);
    const __nv_bfloat16* Qg = g_qb + (size_t)bh * SS * DHH;
    const __nv_bfloat16* Kg = g_kb + (size_t)bh * SS * DHH;
    const __nv_bfloat16* Vg = g_vt + (size_t)bh * DHH * SS;

    // stage Q bf16 tile [128][64] into stage-2 region (offset 65536).
    {
        int row = tid >> 1, half = tid & 1;
        const uint4* src = (const uint4*)(Qg + (size_t)(s0 + row) * DHH + half * 32);
#pragma unroll
        for (int i = 0; i < 4; i++)
            *(uint4*)(arena + 65536 + swz(row, half * 4 + i)) = src[i];
    }
    __syncthreads();

    uint32_t aq[4][4];
    {
        uint32_t r = w * 16 + (lane & 7) + (lane & 8);
#pragma unroll
        for (int ks = 0; ks < 4; ks++) {
            uint32_t cb = ks * 2 + (lane >> 4);
            LDSM4(aq[ks][0], aq[ks][1], aq[ks][2], aq[ks][3], base + 65536 + swz(r, cb));
        }
    }

    const int prow = tid >> 2, pcb = (tid & 3) * 2;
#define PFS(T, stg) do {                                                           \
        uint32_t so = base + (stg) * 32768;                                        \
        int j0 = k_base + (T) * 128;                                               \
        _Pragma("unroll") for (int sub = 0; sub < 2; sub++) {                      \
            uint32_t ko = so + sub * 16384, vo = ko + 8192;                        \
            const __nv_bfloat16* ks_ = Kg + (size_t)(j0 + sub * 64 + prow) * DHH;  \
            const __nv_bfloat16* vs_ = Vg + (size_t)prow * SS + j0 + sub * 64;     \
            _Pragma("unroll") for (int i = 0; i < 2; i++) {                        \
                CPA(ko + swz(prow, pcb + i), ks_ + (pcb + i) * 8);                 \
                CPA(vo + swz(prow, pcb + i), vs_ + (pcb + i) * 8);                 \
            }                                                                      \
        }                                                                          \
        CPC();                                                                     \
    } while (0)

    PFS(0, 0);
    PFS(1, 1);

    float co[8][4];
#pragma unroll
    for (int j = 0; j < 8; j++)
#pragma unroll
        for (int q = 0; q < 4; q++) co[j][q] = 0.f;
    float lacc_lo = 0.f, lacc_hi = 0.f;

    const uint32_t brow = (lane & 7) + ((lane >> 4) << 3);
    const uint32_t bsel = (lane >> 3) & 1;

    const int NT = SS / NSPLIT / 128;   // 8 supertiles
    int st = 0, pfst = 2;
    for (int T = 0; T < NT; T++) {
        if (T < NT - 1) CPW1(); else CPW0();
        __syncthreads();
        if (T < NT - 2) PFS(T + 2, pfst);
        const uint32_t stg = base + st * 32768;
        st = (st == 2) ? 0 : st + 1;
        pfst = (pfst == 2) ? 0 : pfst + 1;

#pragma unroll
        for (int sub = 0; sub < 2; sub++) {
            uint32_t kb = stg + sub * 16384, vb = kb + 8192;

            // S = Q K^T
            float cs[8][4];
#pragma unroll
            for (int j = 0; j < 8; j++)
#pragma unroll
                for (int q = 0; q < 4; q++) cs[j][q] = 0.f;
#pragma unroll
            for (int ks = 0; ks < 4; ks++) {
                uint32_t bc = ks * 2 + bsel;
#pragma unroll
                for (int j = 0; j < 8; j += 2) {
                    uint32_t b0, b1, b2, b3;
                    LDSM4(b0, b1, b2, b3, kb + swz(j * 8 + brow, bc));
                    MMA(cs[j], aq[ks], b0, b1);
                    MMA(cs[j + 1], aq[ks], b2, b3);
                }
            }

            // softmax: exp only; quad reduction deferred
            uint32_t pa[4][4];
#pragma unroll
            for (int j = 0; j < 8; j++) {
                float e0 = ex2(cs[j][0]), e1 = ex2(cs[j][1]);
                float e2 = ex2(cs[j][2]), e3 = ex2(cs[j][3]);
                lacc_lo += e0 + e1; lacc_hi += e2 + e3;
                pa[j >> 1][(j & 1) * 2 + 0] = pkbf(e0, e1);
                pa[j >> 1][(j & 1) * 2 + 1] = pkbf(e2, e3);
            }

            // O += P V
#pragma unroll
            for (int kc = 0; kc < 4; kc++) {
                uint32_t bc = kc * 2 + bsel;
#pragma unroll
                for (int j = 0; j < 8; j += 2) {
                    uint32_t b0, b1, b2, b3;
                    LDSM4(b0, b1, b2, b3, vb + swz(j * 8 + brow, bc));
                    MMA(co[j], pa[kc], b0, b1);
                    MMA(co[j + 1], pa[kc], b2, b3);
                }
            }
        }
    }
#undef PFS

    lacc_lo += __shfl_xor_sync(0xffffffffu, lacc_lo, 1);
    lacc_lo += __shfl_xor_sync(0xffffffffu, lacc_lo, 2);
    lacc_hi += __shfl_xor_sync(0xffffffffu, lacc_hi, 1);
    lacc_hi += __shfl_xor_sync(0xffffffffu, lacc_hi, 2);

    const int g = lane >> 2, c2 = (lane & 3) * 2;
    const int r_lo = s0 + w * 16 + g, r_hi = r_lo + 8;
    __nv_bfloat16* plo = g_po[z] + ((size_t)bh * SS + r_lo) * DHH;
    __nv_bfloat16* phi = g_po[z] + ((size_t)bh * SS + r_hi) * DHH;
#pragma unroll
    for (int j = 0; j < 8; j++) {
        int col = j * 8 + c2;
        *(uint32_t*)(plo + col) = pkbf(co[j][0], co[j][1]);
        *(uint32_t*)(phi + col) = pkbf(co[j][2], co[j][3]);
    }
    g_pl[z][(size_t)bh * SS + r_lo] = lacc_lo;
    g_pl[z][(size_t)bh * SS + r_hi] = lacc_hi;
}

// ---------------- split-K combine (4 partials) ----------------
__global__ void __launch_bounds__(256) combine_k(int n8) {
    int i = blockIdx.x * 256 + threadIdx.x;
    if (i >= n8) return;
    int row = i >> 3;
    float l = g_pl[0][row] + g_pl[1][row] + g_pl[2][row] + g_pl[3][row];
    float inv = 1.f / l;
    uint4 p[NSPLIT];
#pragma unroll
    for (int s = 0; s < NSPLIT; s++) p[s] = ((const uint4*)g_po[s])[i];
    uint4 o;
    uint32_t* op = &o.x;
#pragma unroll
    for (int q = 0; q < 4; q++) {
        float sx = 0.f, sy = 0.f;
#pragma unroll
        for (int s = 0; s < NSPLIT; s++) {
            float2 f = __bfloat1622float2(*(const __nv_bfloat162*)(&p[s].x + q));
            sx += f.x; sy += f.y;
        }
        op[q] = pkbf(sx * inv, sy * inv);
    }
    ((uint4*)g_ob)[i] = o;
}

// ---------------- output projection + bias + residual (GEMM v4) ------------
// grid (64, 10)
__global__ void __launch_bounds__(256, 3) outproj_tc(const float* __restrict__ bias,
                                                     const float* __restrict__ resid,
                                                     float* __restrict__ out) {
    extern __shared__ __align__(128) char arena[];
    const uint32_t base = smem_u32(arena);

    const int tid = threadIdx.x, lane = tid & 31, w = tid >> 5;
    const int wm = (w >> 1) * 32, wn = (w & 1) * 32;
    const int m0 = blockIdx.x * 128, n0 = blockIdx.y * 64;

    const int arow = tid >> 1, apart = tid & 1;
    const uint32_t adst0 = swz(arow >> 1, (arow & 1) * 4 + apart * 2);
    const uint32_t adst1 = swz(arow >> 1, (arow & 1) * 4 + apart * 2 + 1);
    const int bn = tid >> 2, bkc = tid & 3;
    const uint32_t bdst = swz(bn >> 1, (bn & 1) * 4 + bkc);

    const int b_ = m0 >> 12;
    const int s_arow = (m0 + arow) & (SS - 1);

#define OUT_A(c) (g_ob + ((size_t)(b_ * HH + ((c) >> 1)) * SS + s_arow) * DHH + ((c) & 1) * 32 + apart * 16)
#define OUT_B(c) (wob + (size_t)(n0 + bn) * CC + (c) * 32 + bkc * 8)

    FRAG_SETUP();

    float cc[2][4][4];
#pragma unroll
    for (int mi = 0; mi < 2; mi++)
#pragma unroll
        for (int nc = 0; nc < 4; nc++)
#pragma unroll
            for (int q = 0; q < 4; q++) cc[mi][nc][q] = 0.f;

    V4_LOOP(OUT_A, OUT_B)
#undef OUT_A
#undef OUT_B

    const int g = lane >> 2, c2 = (lane & 3) * 2;
#pragma unroll
    for (int mi = 0; mi < 2; mi++) {
        int r_lo = m0 + wm + mi * 16 + g, r_hi = r_lo + 8;
#pragma unroll
        for (int nc = 0; nc < 4; nc++) {
            int col = n0 + wn + nc * 8 + c2;
            float2 bv = *(const float2*)(bias + col);
            float2 rl = *(const float2*)(resid + (size_t)r_lo * CC + col);
            float2 rh = *(const float2*)(resid + (size_t)r_hi * CC + col);
            float2 ol, oh;
            ol.x = cc[mi][nc][0] + bv.x + rl.x; ol.y = cc[mi][nc][1] + bv.y + rl.y;
            oh.x = cc[mi][nc][2] + bv.x + rh.x; oh.y = cc[mi][nc][3] + bv.y + rh.y;
            *(float2*)(out + (size_t)r_lo * CC + col) = ol;
            *(float2*)(out + (size_t)r_hi * CC + col) = oh;
        }
    }
}

extern "C" void kernel_launch(void* const* d_in, const int* in_sizes, int n_in,
                              void* d_out, int out_size) {
    const float* hs    = (const float*)d_in[0];
    const float* Wq    = (const float*)d_in[1];
    const float* Wk    = (const float*)d_in[2];
    const float* Wv    = (const float*)d_in[3];
    const float* Wo    = (const float*)d_in[4];
    const float* b_out = (const float*)d_in[5];
    float* out = (float*)d_out;

    const float qscale = 0.125f * 1.44269504088896340736f;  // 1/sqrt(64) * log2(e)

    cudaFuncSetAttribute(proj_tc, cudaFuncAttributeMaxDynamicSharedMemorySize, 61440);
    cudaFuncSetAttribute(outproj_tc, cudaFuncAttributeMaxDynamicSharedMemorySize, 61440);
    cudaFuncSetAttribute(attn_tc, cudaFuncAttributeMaxDynamicSharedMemorySize, 98304);

    cvt_all<<<(CVT_Q + 255) / 256, 256>>>(hs, Wq, Wk, Wv, Wo, qscale);

    proj_tc<<<dim3(BB * SS / 128, HH, 3), 256, 61440>>>();
    attn_tc<<<dim3(SS / 128, BH, NSPLIT), 256, 98304>>>();
    const int nc8 = NOB / 8;
    combine_k<<<(nc8 + 255) / 256, 256>>>(nc8);
    outproj_tc<<<dim3(BB * SS / 128, HH), 256, 61440>>>(b_out, hs, out);
}